// round 8
// baseline (speedup 1.0000x reference)
#include <cuda_runtime.h>
#include <math.h>

#define B_   16
#define N_   2048
#define K_   16
#define EPS_ 1e-8f

// Output layout (tuple flattened in order):
//   psi_prime : B*N*2  floats  @ 0
//   features  : B*N*5  floats  @ 65536
//   knn_idx   : B*N*16 floats  @ 229376
#define PSI_OFF  0
#define FEAT_OFF (B_ * N_ * 2)
#define KNN_OFF  (B_ * N_ * 2 + B_ * N_ * 5)

typedef unsigned long long u64;
typedef unsigned int u32;

#define SENT 0xFFFFFFFFFFFFFFFFull
#define SUB_ (N_ / 2)          // candidates per thread (2 threads/query)
#define NWIN (SUB_ / 8)        // 8-candidate windows per thread

// SOA candidate data (padded +8 so the software-pipeline prefetch may read
// one window past the end harmlessly).
__device__ float g_x [B_ * N_ + 8];
__device__ float g_y [B_ * N_ + 8];
__device__ float g_sq[B_ * N_ + 8];

// ---- packed f32x2 ops (each half rounds exactly like the scalar op) ----
#define MUL2(o, a, b) asm("mul.rn.f32x2 %0, %1, %2;" : "=l"(o) : "l"(a), "l"(b))
#define ADD2(o, a, b) asm("add.rn.f32x2 %0, %1, %2;" : "=l"(o) : "l"(a), "l"(b))
#define FMA2(o, a, b, c) \
    asm("fma.rn.f32x2 %0, %1, %2, %3;" : "=l"(o) : "l"(a), "l"(b), "l"(c))
#define PACK2(o, lo, hi) \
    asm("mov.b64 %0, {%1, %2};" : "=l"(o) : "f"(lo), "f"(hi))
#define UNPACK2(lo, hi, in) \
    asm("mov.b64 {%0, %1}, %2;" : "=f"(lo), "=f"(hi) : "l"(in))

// ---------------------------------------------------------------------------
// Kernel 1: features + encoder (tiny MLP) + SOA coord scratch.
// ---------------------------------------------------------------------------
__global__ void encode_kernel(const float* __restrict__ coords,
                              const float* __restrict__ demands,
                              const float* __restrict__ capacity,
                              const float* __restrict__ Wa,
                              const float* __restrict__ ba,
                              const float* __restrict__ W1,
                              const float* __restrict__ b1,
                              const float* __restrict__ W2,
                              const float* __restrict__ b2,
                              float* __restrict__ out)
{
    int b = blockIdx.y;
    int n = blockIdx.x * blockDim.x + threadIdx.x;
    if (n >= N_) return;

    __shared__ float sWa[10], sba[2], sW1[80], sb1[16], sW2[16], sb2_s;
    int t = threadIdx.x;
    if (t < 10) sWa[t] = Wa[t];
    if (t < 2)  sba[t] = ba[t];
    if (t < 80) sW1[t] = W1[t];
    if (t < 16) { sb1[t] = b1[t]; sW2[t] = W2[t]; }
    if (t == 0) sb2_s = b2[0];
    __syncthreads();

    const float* cp = coords + ((long long)b * N_ + n) * 2;
    float x = cp[0], y = cp[1];

    // SOA scratch for knn; sq = rn(rn(x*x) + rn(y*y)) (reference rounding)
    float sq = __fadd_rn(__fmul_rn(x, x), __fmul_rn(y, y));
    g_x [b * N_ + n] = x;
    g_y [b * N_ + n] = y;
    g_sq[b * N_ + n] = sq;

    float dx0 = coords[(long long)b * N_ * 2 + 0];
    float dy0 = coords[(long long)b * N_ * 2 + 1];
    float rx = x - dx0, ry = y - dy0;
    float dist = sqrtf(rx * rx + ry * ry + EPS_);
    float ang  = atan2f(ry, rx);
    float dem  = demands[(long long)b * N_ + n] / capacity[b];

    float f0 = x, f1 = y, f2 = dem, f3 = dist, f4 = ang;

    float* fo = out + FEAT_OFF + ((long long)b * N_ + n) * 5;
    fo[0] = f0; fo[1] = f1; fo[2] = f2; fo[3] = f3; fo[4] = f4;

    float p0 = sba[0] + f0*sWa[0] + f1*sWa[1] + f2*sWa[2] + f3*sWa[3] + f4*sWa[4];
    float p1 = sba[1] + f0*sWa[5] + f1*sWa[6] + f2*sWa[7] + f3*sWa[8] + f4*sWa[9];
    float nrm = sqrtf(p0 * p0 + p1 * p1);
    float inv = 1.0f / (nrm + EPS_);
    p0 *= inv; p1 *= inv;

    float theta = sb2_s;
    #pragma unroll
    for (int h = 0; h < 16; ++h) {
        const float* w = sW1 + h * 5;
        float a = sb1[h] + f0*w[0] + f1*w[1] + f2*w[2] + f3*w[3] + f4*w[4];
        theta += tanhf(a) * sW2[h];
    }
    float c = cosf(theta), s = sinf(theta);

    float* po = out + PSI_OFF + ((long long)b * N_ + n) * 2;
    po[0] = c * p0 - s * p1;
    po[1] = s * p0 + c * p1;
}

// ---------------------------------------------------------------------------
// KNN helpers
// ---------------------------------------------------------------------------

// Monotone map: float bits -> u32 whose unsigned order == float order.
__device__ __forceinline__ u32 fmap(u32 b) {
    return b ^ ((u32)((int)b >> 31) | 0x80000000u);
}

// Flush: read raw (f32bits<<32|j) entries from this lane's smem buffer
// (interleaved stride 32), convert to total-order keys, bitonic-sort-16,
// merge into sorted L (min-pair + clean), tighten tau. Exact ties:
// keys are (fmap(d2), j) lexicographic.
__device__ __forceinline__ void flush16(u64* L, const u64* sbase, int& n,
                                        float& tau_f)
{
    u64 s[16];
    #pragma unroll
    for (int i = 0; i < 16; ++i) {
        u64 raw = sbase[i * 32];
        u64 key = ((u64)fmap((u32)(raw >> 32)) << 32) | (u32)raw;
        s[i] = (i < n) ? key : SENT;
    }

    // Bitonic sort 16, ascending (proven network).
    #pragma unroll
    for (int k = 2; k <= 16; k <<= 1) {
        #pragma unroll
        for (int j = k >> 1; j > 0; j >>= 1) {
            #pragma unroll
            for (int i = 0; i < 16; ++i) {
                int l = i ^ j;
                if (l > i) {
                    bool up = ((i & k) == 0);
                    u64 a = s[i], b = s[l];
                    bool sw = up ? (a > b) : (a < b);
                    s[i] = sw ? b : a;
                    s[l] = sw ? a : b;
                }
            }
        }
    }

    // Lowest 16 of (L asc, s asc): min-pair -> bitonic, then clean.
    #pragma unroll
    for (int i = 0; i < 16; ++i) {
        u64 a = L[i], b = s[15 - i];
        L[i] = (a < b) ? a : b;
    }
    #pragma unroll
    for (int j = 8; j > 0; j >>= 1) {
        #pragma unroll
        for (int i = 0; i < 16; ++i) {
            int l = i ^ j;
            if (l > i) {
                u64 a = L[i], b = L[l];
                bool sw = a > b;
                L[i] = sw ? b : a;
                L[l] = sw ? a : b;
            }
        }
    }

    // tau = d2 of current 16th (inverse fmap). L is fully real by the first
    // flush (tau=inf until then, so the first 16 candidates all appended).
    u32 h = (u32)(L[15] >> 32);
    h = (h & 0x80000000u) ? (h ^ 0x80000000u) : ~h;
    tau_f = __uint_as_float(h);
    n = 0;
}

// ---------------------------------------------------------------------------
// Kernel 2: KNN top-16, buffered deferred selection, 2 threads per query.
// Block = 1 warp (32 thr, 16 queries), 2048 blocks: finest balance grain.
// Software-pipelined SOA loads (prefetch next 8-candidate window), packed
// f32x2 distance math (bit-exact per half vs the reference gemm lowering:
//   t=rn(xq*xj); dot=fma(yq,yj,t); s=rn(sqq+sqj); d2=fma(-2,dot,s) ),
// smem append buffer, rare warp-synchronized flush, partner-lane merge.
// ---------------------------------------------------------------------------
__global__ void __launch_bounds__(32, 14)
knn_kernel(float* __restrict__ out_knn)
{
    __shared__ u64 sbuf[16 * 32];   // [slot][lane], conflict-free u64

    int qid = blockIdx.x * 16 + (threadIdx.x >> 1);  // global query id
    int p   = threadIdx.x & 1;                       // candidate-half
    int b   = qid >> 11;
    int q   = qid & (N_ - 1);

    const float* bx = g_x  + b * N_;
    const float* by = g_y  + b * N_;
    const float* bs = g_sq + b * N_;

    float xq  = __ldg(&bx[q]);
    float yq  = __ldg(&by[q]);
    float sqq = __ldg(&bs[q]);

    u64 xq2, yq2, sq2, m22;
    PACK2(xq2, xq, xq);
    PACK2(yq2, yq, yq);
    PACK2(sq2, sqq, sqq);
    PACK2(m22, -2.0f, -2.0f);

    const ulonglong2* xp = (const ulonglong2*)(bx + p * SUB_);
    const ulonglong2* yp = (const ulonglong2*)(by + p * SUB_);
    const ulonglong2* sp = (const ulonglong2*)(bs + p * SUB_);
    int jbase = p * SUB_;

    u64 L[16];
    #pragma unroll
    for (int k = 0; k < 16; ++k) L[k] = SENT;

    u64* sb = sbuf + threadIdx.x;   // this lane's buffer, stride 32
    int n = 0;
    float tau_f = 3.4e38f;

    #define APPEND(ev, jv) \
        do { if ((ev) <= tau_f) { \
            sb[n * 32] = ((u64)__float_as_uint(ev) << 32) | (u32)(jv); \
            n++; } } while (0)

    // software pipeline: cur holds window i, prefetch window i+1
    ulonglong2 cxa = xp[0], cxb = xp[1];
    ulonglong2 cya = yp[0], cyb = yp[1];
    ulonglong2 csa = sp[0], csb = sp[1];

    #pragma unroll 2
    for (int i = 0; i < NWIN; ++i) {
        // prefetch next window (padded arrays make the last read safe)
        ulonglong2 nxa = xp[2 * i + 2], nxb = xp[2 * i + 3];
        ulonglong2 nya = yp[2 * i + 2], nyb = yp[2 * i + 3];
        ulonglong2 nsa = sp[2 * i + 2], nsb = sp[2 * i + 3];

        // packed distances: 4 pairs of candidates
        u64 t, d, s2, r;
        float e0, e1, e2, e3, e4, e5, e6, e7;
        MUL2(t, xq2, cxa.x); FMA2(d, yq2, cya.x, t);
        ADD2(s2, sq2, csa.x); FMA2(r, m22, d, s2); UNPACK2(e0, e1, r);
        MUL2(t, xq2, cxa.y); FMA2(d, yq2, cya.y, t);
        ADD2(s2, sq2, csa.y); FMA2(r, m22, d, s2); UNPACK2(e2, e3, r);
        MUL2(t, xq2, cxb.x); FMA2(d, yq2, cyb.x, t);
        ADD2(s2, sq2, csb.x); FMA2(r, m22, d, s2); UNPACK2(e4, e5, r);
        MUL2(t, xq2, cxb.y); FMA2(d, yq2, cyb.y, t);
        ADD2(s2, sq2, csb.y); FMA2(r, m22, d, s2); UNPACK2(e6, e7, r);

        int j0 = jbase + 8 * i;
        // self-exclusion, one rare branch per 8-window
        if ((unsigned)(q - j0) < 8u) {
            int rr = q - j0;
            if (rr == 0) e0 = 2.0e30f;  if (rr == 1) e1 = 2.0e30f;
            if (rr == 2) e2 = 2.0e30f;  if (rr == 3) e3 = 2.0e30f;
            if (rr == 4) e4 = 2.0e30f;  if (rr == 5) e5 = 2.0e30f;
            if (rr == 6) e6 = 2.0e30f;  if (rr == 7) e7 = 2.0e30f;
        }

        // '<=' so equal-d2/smaller-j candidates always enter; the u64-key
        // flush resolves ties exactly (top_k stable order).
        APPEND(e0, j0);     APPEND(e1, j0 + 1);
        APPEND(e2, j0 + 2); APPEND(e3, j0 + 3);
        APPEND(e4, j0 + 4); APPEND(e5, j0 + 5);
        APPEND(e6, j0 + 6); APPEND(e7, j0 + 7);

        // n <= 8 at entry, +8 -> 16 max: no overflow of the 16-slot buffer.
        if (__ballot_sync(0xffffffffu, n >= 9))
            flush16(L, sb, n, tau_f);

        cxa = nxa; cxb = nxb; cya = nya; cyb = nyb; csa = nsa; csb = nsb;
    }

    flush16(L, sb, n, tau_f);   // drain

    // Merge partner halves (lane^1): min-pair vs partner's reversed sorted
    // list -> bitonic -> clean. Both lanes end with the identical top-16.
    #pragma unroll
    for (int i = 0; i < 16; ++i) {
        u64 other = __shfl_xor_sync(0xffffffffu, L[15 - i], 1);
        u64 a = L[i];
        L[i] = (a < other) ? a : other;
    }
    #pragma unroll
    for (int j = 8; j > 0; j >>= 1) {
        #pragma unroll
        for (int i = 0; i < 16; ++i) {
            int l = i ^ j;
            if (l > i) {
                u64 a = L[i], b2 = L[l];
                bool sw = a > b2;
                L[i] = sw ? b2 : a;
                L[l] = sw ? a : b2;
            }
        }
    }

    // Each partner lane writes half the 16 outputs.
    float* o = out_knn + ((long long)b * N_ + q) * K_;
    #pragma unroll
    for (int k = 0; k < 8; ++k) {
        int kk = p * 8 + k;
        o[kk] = (float)(u32)(L[kk] & 0xFFFFFFFFu);
    }
    #undef APPEND
}

// ---------------------------------------------------------------------------
extern "C" void kernel_launch(void* const* d_in, const int* in_sizes, int n_in,
                              void* d_out, int out_size)
{
    const float* coords   = (const float*)d_in[0];
    const float* demands  = (const float*)d_in[1];
    const float* capacity = (const float*)d_in[2];
    const float* Wa       = (const float*)d_in[3];
    const float* ba       = (const float*)d_in[4];
    const float* W1       = (const float*)d_in[5];
    const float* b1       = (const float*)d_in[6];
    const float* W2       = (const float*)d_in[7];
    const float* b2       = (const float*)d_in[8];
    float* out = (float*)d_out;

    encode_kernel<<<dim3(N_ / 256, B_), 256>>>(coords, demands, capacity,
                                               Wa, ba, W1, b1, W2, b2, out);
    // B*N queries x 2 threads each; 32-thread blocks (16 queries/block)
    knn_kernel<<<dim3(B_ * N_ * 2 / 32), 32>>>(out + KNN_OFF);
}